// round 1
// baseline (speedup 1.0000x reference)
#include <cuda_runtime.h>
#include <cuda_bf16.h>

// RandomAttention: B=2, S=2048, NH=8, H=64, NKEYS=64
// inputs: q (B,S,NH,H) f32, k (B,S,NH,H) f32, v (B,S,NH,H) f32, indices (B,S,NKEYS) i32
// output: z (B,S,NH,H) f32
//
// One CTA per (b,q). 8 warps = 8 heads. Indices shared across heads via smem.
// Per head: 64 coalesced 256B k-row loads -> dot via butterfly reduce -> softmax
// over 64 keys -> 64 coalesced v-row loads -> weighted sum.

#define B_  2
#define S_  2048
#define NH_ 8
#define H_  64
#define NK_ 64

__global__ __launch_bounds__(256, 8)
void ra_kernel(const float* __restrict__ q,
               const float* __restrict__ k,
               const float* __restrict__ v,
               const int*   __restrict__ indices,
               float*       __restrict__ out)
{
    const int bq   = blockIdx.x;          // b * S_ + qpos
    const int head = threadIdx.x >> 5;    // 0..7
    const int lane = threadIdx.x & 31;
    const int base_b = (bq >> 11) << 11;  // b * S_  (S_ = 2048)

    __shared__ int   s_idx[NK_];
    __shared__ float s_sc[NH_][NK_];

    if (threadIdx.x < NK_)
        s_idx[threadIdx.x] = indices[bq * NK_ + threadIdx.x];
    __syncthreads();

    const float scale = 0.125f;  // 64^-0.5
    const float2 qv = *reinterpret_cast<const float2*>(
        &q[(bq * NH_ + head) * H_ + 2 * lane]);
    const float q0 = qv.x * scale;
    const float q1 = qv.y * scale;

    // ---- scores: dot(q, k_gathered[j]) for 64 keys ----
    #pragma unroll 8
    for (int j = 0; j < NK_; ++j) {
        const int row = base_b + s_idx[j];
        const float2 kv = *reinterpret_cast<const float2*>(
            &k[(row * NH_ + head) * H_ + 2 * lane]);
        float p = q0 * kv.x + q1 * kv.y;
        p += __shfl_xor_sync(0xffffffffu, p, 16);
        p += __shfl_xor_sync(0xffffffffu, p, 8);
        p += __shfl_xor_sync(0xffffffffu, p, 4);
        p += __shfl_xor_sync(0xffffffffu, p, 2);
        p += __shfl_xor_sync(0xffffffffu, p, 1);
        if (lane == 0) s_sc[head][j] = p;
    }
    __syncwarp();

    // ---- softmax over 64 keys (2 per lane) ----
    float a = s_sc[head][lane];
    float c = s_sc[head][lane + 32];
    float m = fmaxf(a, c);
    m = fmaxf(m, __shfl_xor_sync(0xffffffffu, m, 16));
    m = fmaxf(m, __shfl_xor_sync(0xffffffffu, m, 8));
    m = fmaxf(m, __shfl_xor_sync(0xffffffffu, m, 4));
    m = fmaxf(m, __shfl_xor_sync(0xffffffffu, m, 2));
    m = fmaxf(m, __shfl_xor_sync(0xffffffffu, m, 1));
    const float e0 = __expf(a - m);
    const float e1 = __expf(c - m);
    float s = e0 + e1;
    s += __shfl_xor_sync(0xffffffffu, s, 16);
    s += __shfl_xor_sync(0xffffffffu, s, 8);
    s += __shfl_xor_sync(0xffffffffu, s, 4);
    s += __shfl_xor_sync(0xffffffffu, s, 2);
    s += __shfl_xor_sync(0xffffffffu, s, 1);
    const float inv = 1.0f / s;
    s_sc[head][lane]      = e0 * inv;
    s_sc[head][lane + 32] = e1 * inv;
    __syncwarp();

    // ---- weighted sum over gathered v rows ----
    float z0 = 0.0f, z1 = 0.0f;
    #pragma unroll 8
    for (int j = 0; j < NK_; ++j) {
        const int row = base_b + s_idx[j];
        const float wj = s_sc[head][j];
        const float2 vv = *reinterpret_cast<const float2*>(
            &v[(row * NH_ + head) * H_ + 2 * lane]);
        z0 = fmaf(wj, vv.x, z0);
        z1 = fmaf(wj, vv.y, z1);
    }

    float2 o;
    o.x = z0;
    o.y = z1;
    *reinterpret_cast<float2*>(&out[(bq * NH_ + head) * H_ + 2 * lane]) = o;
}

extern "C" void kernel_launch(void* const* d_in, const int* in_sizes, int n_in,
                              void* d_out, int out_size)
{
    const float* q   = (const float*)d_in[0];
    const float* k   = (const float*)d_in[1];
    const float* v   = (const float*)d_in[2];
    const int* indices = (const int*)d_in[3];
    float* out = (float*)d_out;

    ra_kernel<<<B_ * S_, 256>>>(q, k, v, indices, out);
}

// round 3
// speedup vs baseline: 2.0600x; 2.0600x over previous
#include <cuda_runtime.h>
#include <cuda_fp16.h>

// RandomAttention: B=2, S=2048, NH=8, H=64, NKEYS=64
// inputs: q,k,v (B,S,NH,H) f32; indices (B,S,NKEYS) i32; out (B,S,NH,H) f32
//
// Strategy: L1/MIO-wavefront bound. Stage K,V as fp16 (halves gather bytes),
// score pass loads 4 key rows per warp-wide uint4 load (8 lanes/row) with a
// 3-shuffle segmented reduction (vs 5 shuffles/key before).

#define B_  2
#define S_  2048
#define NH_ 8
#define H_  64
#define NK_ 64
#define KV_ELEMS (B_ * S_ * NH_ * H_)   // 2,097,152

__device__ __half g_kh[KV_ELEMS];
__device__ __half g_vh[KV_ELEMS];

__global__ __launch_bounds__(256)
void convert_kernel(const float* __restrict__ k, const float* __restrict__ v)
{
    const int t = blockIdx.x * blockDim.x + threadIdx.x;  // one float4 per thread
    if (t >= KV_ELEMS / 4) return;
    const float4 a = reinterpret_cast<const float4*>(k)[t];
    const float4 b = reinterpret_cast<const float4*>(v)[t];
    __half2* kh2 = reinterpret_cast<__half2*>(g_kh);
    __half2* vh2 = reinterpret_cast<__half2*>(g_vh);
    kh2[2 * t]     = __floats2half2_rn(a.x, a.y);
    kh2[2 * t + 1] = __floats2half2_rn(a.z, a.w);
    vh2[2 * t]     = __floats2half2_rn(b.x, b.y);
    vh2[2 * t + 1] = __floats2half2_rn(b.z, b.w);
}

__global__ __launch_bounds__(256, 4)
void ra_kernel(const float* __restrict__ q,
               const int*   __restrict__ indices,
               float*       __restrict__ out)
{
    const int bq   = blockIdx.x;
    const int head = threadIdx.x >> 5;
    const int lane = threadIdx.x & 31;
    const int sub  = lane & 7;     // position within key row (8 lanes/row)
    const int grp  = lane >> 3;    // which of 4 rows this lane serves

    __shared__ int   s_off[NK_];          // precomputed half-offsets: row*512
    __shared__ float s_sc[NH_][NK_];

    if (threadIdx.x < NK_) {
        const int b = bq >> 11;           // bq / S_
        const int row = (b << 11) + indices[bq * NK_ + threadIdx.x];
        s_off[threadIdx.x] = row << 9;    // row * NH_*H_ (=512) halves
    }
    __syncthreads();

    // q slice this lane needs for the score pass: dims [sub*8, sub*8+8)
    const float* qrow = q + (bq * NH_ + head) * H_;
    const float scale = 0.125f;           // H^-0.5
    float4 qa = *reinterpret_cast<const float4*>(qrow + sub * 8);
    float4 qb = *reinterpret_cast<const float4*>(qrow + sub * 8 + 4);
    qa.x *= scale; qa.y *= scale; qa.z *= scale; qa.w *= scale;
    qb.x *= scale; qb.y *= scale; qb.z *= scale; qb.w *= scale;

    const int hoff = head * H_;

    // ---- score pass: 4 key rows per warp-wide load ----
    #pragma unroll 8
    for (int j = 0; j < NK_ / 4; ++j) {
        const int key = 4 * j + grp;
        const uint4 raw = *reinterpret_cast<const uint4*>(
            g_kh + s_off[key] + hoff + sub * 8);
        const __half2* h = reinterpret_cast<const __half2*>(&raw);
        const float2 f0 = __half22float2(h[0]);
        const float2 f1 = __half22float2(h[1]);
        const float2 f2 = __half22float2(h[2]);
        const float2 f3 = __half22float2(h[3]);
        float p = qa.x * f0.x + qa.y * f0.y
                + qa.z * f1.x + qa.w * f1.y
                + qb.x * f2.x + qb.y * f2.y
                + qb.z * f3.x + qb.w * f3.y;
        // segmented reduction within each 8-lane group (reduces 4 keys at once)
        p += __shfl_xor_sync(0xffffffffu, p, 4);
        p += __shfl_xor_sync(0xffffffffu, p, 2);
        p += __shfl_xor_sync(0xffffffffu, p, 1);
        if (sub == 0) s_sc[head][key] = p;
    }
    __syncwarp();

    // ---- softmax over 64 keys (2 per lane) ----
    const float a = s_sc[head][lane];
    const float c = s_sc[head][lane + 32];
    float m = fmaxf(a, c);
    m = fmaxf(m, __shfl_xor_sync(0xffffffffu, m, 16));
    m = fmaxf(m, __shfl_xor_sync(0xffffffffu, m, 8));
    m = fmaxf(m, __shfl_xor_sync(0xffffffffu, m, 4));
    m = fmaxf(m, __shfl_xor_sync(0xffffffffu, m, 2));
    m = fmaxf(m, __shfl_xor_sync(0xffffffffu, m, 1));
    const float e0 = __expf(a - m);
    const float e1 = __expf(c - m);
    float s = e0 + e1;
    s += __shfl_xor_sync(0xffffffffu, s, 16);
    s += __shfl_xor_sync(0xffffffffu, s, 8);
    s += __shfl_xor_sync(0xffffffffu, s, 4);
    s += __shfl_xor_sync(0xffffffffu, s, 2);
    s += __shfl_xor_sync(0xffffffffu, s, 1);
    const float inv = 1.0f / s;
    s_sc[head][lane]      = e0 * inv;
    s_sc[head][lane + 32] = e1 * inv;
    __syncwarp();

    // ---- weighted V sum: lane owns dims 2*lane, 2*lane+1 ----
    float z0 = 0.0f, z1 = 0.0f;
    const int doff = hoff + 2 * lane;
    #pragma unroll 8
    for (int j = 0; j < NK_; ++j) {
        const __half2 hv = *reinterpret_cast<const __half2*>(
            g_vh + s_off[j] + doff);
        const float2 fv = __half22float2(hv);
        const float w = s_sc[head][j];
        z0 = fmaf(w, fv.x, z0);
        z1 = fmaf(w, fv.y, z1);
    }

    float2 o; o.x = z0; o.y = z1;
    *reinterpret_cast<float2*>(&out[(bq * NH_ + head) * H_ + 2 * lane]) = o;
}

extern "C" void kernel_launch(void* const* d_in, const int* in_sizes, int n_in,
                              void* d_out, int out_size)
{
    const float* q = (const float*)d_in[0];
    const float* k = (const float*)d_in[1];
    const float* v = (const float*)d_in[2];
    const int* indices = (const int*)d_in[3];
    float* out = (float*)d_out;

    convert_kernel<<<KV_ELEMS / 4 / 256, 256>>>(k, v);
    ra_kernel<<<B_ * S_, 256>>>(q, indices, out);
}